// round 4
// baseline (speedup 1.0000x reference)
#include <cuda_runtime.h>
#include <math.h>

#define BB 4096
#define KK 32
#define DD 1024
#define RR 128

// context scratch (allocation-free rule: device global)
__device__ float g_ctx[(size_t)BB * DD];

// ---------------------------------------------------------------------------
// Kernel 1: fused LN + scores GEMM + dist weighting + softmax + threshold +
//           self_w / nb_w outputs + context
// One CTA per b. 256 threads. Each thread owns one output column e per
// e-chunk (4 chunks of 256 cover D=1024); softmax over the 33 combined rows
// is thread-local.
// ---------------------------------------------------------------------------
__global__ __launch_bounds__(256, 1)
void fused_attn_kernel(const float* __restrict__ tgt,       // (B, D)
                       const float* __restrict__ nbr,       // (B, K, D)
                       const float* __restrict__ dist,      // (B, K)
                       const float* __restrict__ beta_p,    // scalar
                       const float* __restrict__ ln_scale,  // (D,)
                       const float* __restrict__ ln_bias,   // (D,)
                       const float* __restrict__ w_self,    // (D, D)
                       const float* __restrict__ b_self,    // (D,)
                       const float* __restrict__ w_nb,      // (D, D)
                       const float* __restrict__ b_nb,      // (D,)
                       float* __restrict__ out_selfw,       // (B, D)
                       float* __restrict__ out_nbw)         // (B, K, D)
{
    extern __shared__ float smem[];
    float* xn     = smem;                 // 33 * 1024   (LN'd rows)
    float* ws_s   = xn   + 33 * 1024;     // 256 * 33    (w_self tile, pad 33)
    float* wn_s   = ws_s + 256 * 33;      // 256 * 33    (w_nb tile,   pad 33)
    float* sc_s   = wn_s + 256 * 33;      // 1024
    float* bi_s   = sc_s + 1024;          // 1024
    float* dist_s = bi_s + 1024;          // 32

    const int b    = blockIdx.x;
    const int tid  = threadIdx.x;
    const int wid  = tid >> 5;
    const int lane = tid & 31;

    // ---- preload ln scale/bias + distance weights ----
    for (int i = tid; i < DD; i += 256) {
        sc_s[i] = __ldg(ln_scale + i);
        bi_s[i] = __ldg(ln_bias + i);
    }
    if (tid < KK) {
        float dv = __ldg(dist + (size_t)b * KK + tid);
        dist_s[tid] = expf(dv * (-2.0f / (100.0f + 1e-8f)));
    }
    __syncthreads();

    // ---- LayerNorm: row 0 = target, rows 1..32 = neighbors ----
    for (int row = wid; row < 33; row += 8) {
        const float* src = (row == 0) ? (tgt + (size_t)b * DD)
                                      : (nbr + ((size_t)b * KK + (row - 1)) * DD);
        const float4* src4 = (const float4*)src;
        float4 v[8];
        float s = 0.f, q = 0.f;
        #pragma unroll
        for (int j = 0; j < 8; ++j) {
            v[j] = __ldg(src4 + j * 32 + lane);
            s += v[j].x + v[j].y + v[j].z + v[j].w;
            q += v[j].x * v[j].x + v[j].y * v[j].y + v[j].z * v[j].z + v[j].w * v[j].w;
        }
        #pragma unroll
        for (int o = 16; o > 0; o >>= 1) {
            s += __shfl_xor_sync(0xffffffffu, s, o);
            q += __shfl_xor_sync(0xffffffffu, q, o);
        }
        float mu   = s * (1.0f / 1024.0f);
        float var  = q * (1.0f / 1024.0f) - mu * mu;
        float rstd = rsqrtf(var + 1e-5f);
        float* dst = xn + row * 1024;
        #pragma unroll
        for (int j = 0; j < 8; ++j) {
            int d = (j * 32 + lane) * 4;
            dst[d + 0] = (v[j].x - mu) * rstd * sc_s[d + 0] + bi_s[d + 0];
            dst[d + 1] = (v[j].y - mu) * rstd * sc_s[d + 1] + bi_s[d + 1];
            dst[d + 2] = (v[j].z - mu) * rstd * sc_s[d + 2] + bi_s[d + 2];
            dst[d + 3] = (v[j].w - mu) * rstd * sc_s[d + 3] + bi_s[d + 3];
        }
    }
    __syncthreads();

    const float beta = __ldg(beta_p);

    // ---- main: 4 e-chunks of 256 columns, one column per thread ----
    for (int e0 = 0; e0 < DD; e0 += 256) {
        float acc[33];
        #pragma unroll
        for (int m = 0; m < 33; ++m) acc[m] = 0.f;

        for (int d0 = 0; d0 < DD; d0 += 32) {
            __syncthreads();
            // Stage weight tiles (256 e-rows x 32 d-cols), coalesced float4
            // global loads, scalar SMEM stores into stride-33 padded layout.
            {
                const float4* wsrc = (const float4*)w_self;
                const float4* wnsc = (const float4*)w_nb;
                const int dq = d0 >> 2;
                #pragma unroll
                for (int j = 0; j < 8; ++j) {
                    int i  = tid + 256 * j;   // 0..2047
                    int er = i >> 3;          // 0..255
                    int c4 = i & 7;           // 0..7
                    size_t gi = (size_t)(e0 + er) * 256 + dq + c4;
                    float4 a = __ldg(wsrc + gi);
                    float4 c = __ldg(wnsc + gi);
                    int so = er * 33 + c4 * 4;
                    ws_s[so + 0] = a.x; ws_s[so + 1] = a.y;
                    ws_s[so + 2] = a.z; ws_s[so + 3] = a.w;
                    wn_s[so + 0] = c.x; wn_s[so + 1] = c.y;
                    wn_s[so + 2] = c.z; wn_s[so + 3] = c.w;
                }
            }
            __syncthreads();

            // Compute: per 4-d group, 8 scalar w loads + 33 float4 broadcast
            // xn loads + 132 FFMA -> FFMA-pipe bound.
            #pragma unroll 2
            for (int d4 = 0; d4 < 8; ++d4) {
                float wsv0 = ws_s[tid * 33 + d4 * 4 + 0];
                float wsv1 = ws_s[tid * 33 + d4 * 4 + 1];
                float wsv2 = ws_s[tid * 33 + d4 * 4 + 2];
                float wsv3 = ws_s[tid * 33 + d4 * 4 + 3];
                float wnv0 = wn_s[tid * 33 + d4 * 4 + 0];
                float wnv1 = wn_s[tid * 33 + d4 * 4 + 1];
                float wnv2 = wn_s[tid * 33 + d4 * 4 + 2];
                float wnv3 = wn_s[tid * 33 + d4 * 4 + 3];
                {
                    const float4 x0 = *(const float4*)&xn[d0 + d4 * 4];
                    acc[0] += x0.x * wsv0;
                    acc[0] += x0.y * wsv1;
                    acc[0] += x0.z * wsv2;
                    acc[0] += x0.w * wsv3;
                }
                #pragma unroll
                for (int m = 1; m < 33; ++m) {
                    const float4 xm = *(const float4*)&xn[m * 1024 + d0 + d4 * 4];
                    acc[m] += xm.x * wnv0;
                    acc[m] += xm.y * wnv1;
                    acc[m] += xm.z * wnv2;
                    acc[m] += xm.w * wnv3;
                }
            }
        }

        // ---- epilogue: bias, distance weight, softmax, threshold, outputs ----
        const int e = e0 + tid;
        acc[0] += __ldg(b_self + e);
        const float bn = __ldg(b_nb + e);
        #pragma unroll
        for (int m = 1; m < 33; ++m) acc[m] = (acc[m] + bn) * dist_s[m - 1];

        float mx = acc[0];
        #pragma unroll
        for (int m = 1; m < 33; ++m) mx = fmaxf(mx, acc[m]);
        float sum = 0.f;
        #pragma unroll
        for (int m = 0; m < 33; ++m) { acc[m] = expf(acc[m] - mx); sum += acc[m]; }
        const float inv = 1.0f / sum;
        #pragma unroll
        for (int m = 0; m < 33; ++m) {
            float w = acc[m] * inv;
            acc[m] = (fabsf(w) >= 0.01f) ? w : 0.0f;
        }

        out_selfw[(size_t)b * DD + e] = acc[0];
        float ctx  = beta * acc[0] * xn[e];
        float nsum = 0.f;
        #pragma unroll
        for (int m = 1; m < 33; ++m) {
            out_nbw[((size_t)b * KK + (m - 1)) * DD + e] = acc[m];
            nsum += acc[m] * xn[m * 1024 + e];
        }
        ctx += (1.0f - beta) * nsum;
        g_ctx[(size_t)b * DD + e] = ctx;
    }
}

// ---------------------------------------------------------------------------
// Kernel 2: reduced = leaky_relu(context @ w_red^T + b_red)   (4096x128x1024)
// 128 CTAs, each computes a 32(b) x 128(r) tile.
// ---------------------------------------------------------------------------
__global__ __launch_bounds__(256)
void reduce_kernel(const float* __restrict__ w_red,   // (R, D)
                   const float* __restrict__ b_red,   // (R,)
                   float* __restrict__ out_red)       // (B, R)
{
    __shared__ float ctx_s[32 * 33];
    __shared__ float w_s[128 * 33];

    const int t  = threadIdx.x;
    const int b0 = blockIdx.x * 32;
    const int tb = t >> 4;   // 0..15
    const int tr = t & 15;   // 0..15

    float acc[2][8];
    #pragma unroll
    for (int i = 0; i < 8; ++i) { acc[0][i] = 0.f; acc[1][i] = 0.f; }

    for (int d0 = 0; d0 < DD; d0 += 32) {
        __syncthreads();
        #pragma unroll
        for (int j = 0; j < 4; ++j) {
            int i = t + 256 * j;          // 0..1023
            int row = i >> 5, col = i & 31;
            ctx_s[row * 33 + col] = g_ctx[(size_t)(b0 + row) * DD + d0 + col];
        }
        #pragma unroll
        for (int j = 0; j < 16; ++j) {
            int i = t + 256 * j;          // 0..4095
            int row = i >> 5, col = i & 31;
            w_s[row * 33 + col] = __ldg(w_red + (size_t)row * DD + d0 + col);
        }
        __syncthreads();

        #pragma unroll
        for (int dl = 0; dl < 32; ++dl) {
            float c0 = ctx_s[tb * 33 + dl];
            float c1 = ctx_s[(tb + 16) * 33 + dl];
            #pragma unroll
            for (int i = 0; i < 8; ++i) {
                float wv = w_s[(tr + 16 * i) * 33 + dl];
                acc[0][i] += c0 * wv;
                acc[1][i] += c1 * wv;
            }
        }
    }

    #pragma unroll
    for (int i = 0; i < 8; ++i) {
        int r = tr + 16 * i;
        float bias = __ldg(b_red + r);
        float v0 = acc[0][i] + bias;
        float v1 = acc[1][i] + bias;
        v0 = v0 > 0.f ? v0 : 0.01f * v0;
        v1 = v1 > 0.f ? v1 : 0.01f * v1;
        out_red[(size_t)(b0 + tb) * RR + r]      = v0;
        out_red[(size_t)(b0 + tb + 16) * RR + r] = v1;
    }
}

// ---------------------------------------------------------------------------
extern "C" void kernel_launch(void* const* d_in, const int* in_sizes, int n_in,
                              void* d_out, int out_size)
{
    (void)in_sizes; (void)n_in; (void)out_size;

    const float* tgt      = (const float*)d_in[0];
    const float* nbr      = (const float*)d_in[1];
    const float* dist     = (const float*)d_in[2];
    const float* beta_p   = (const float*)d_in[3];
    const float* ln_scale = (const float*)d_in[4];
    const float* ln_bias  = (const float*)d_in[5];
    const float* w_self   = (const float*)d_in[6];
    const float* b_self   = (const float*)d_in[7];
    const float* w_nb     = (const float*)d_in[8];
    const float* b_nb     = (const float*)d_in[9];
    const float* w_red    = (const float*)d_in[10];
    const float* b_red    = (const float*)d_in[11];

    float* out        = (float*)d_out;
    float* out_red    = out;                                  // B*R
    float* out_selfw  = out + (size_t)BB * RR;                // B*D
    float* out_nbw    = out_selfw + (size_t)BB * DD;          // B*K*D

    const size_t smem1 = (size_t)(33 * 1024 + 2 * 256 * 33 + 2 * 1024 + 32) * sizeof(float);
    cudaFuncSetAttribute(fused_attn_kernel,
                         cudaFuncAttributeMaxDynamicSharedMemorySize, (int)smem1);

    fused_attn_kernel<<<BB, 256, smem1>>>(tgt, nbr, dist, beta_p, ln_scale, ln_bias,
                                          w_self, b_self, w_nb, b_nb,
                                          out_selfw, out_nbw);
    reduce_kernel<<<BB / 32, 256>>>(w_red, b_red, out_red);
}

// round 6
// speedup vs baseline: 2.3426x; 2.3426x over previous
#include <cuda_runtime.h>
#include <math.h>
#include <stdint.h>

#define BB 4096
#define KK 32
#define DD 1024
#define RR 128

// ---------------- device scratch (allocation-free rule: __device__ globals) ----
__device__ float g_xnt[(size_t)BB * DD];        // LN'd target (fp32)
__device__ float g_xnn[(size_t)BB * KK * DD];   // LN'd neighbors (fp32)
__device__ float g_snb[(size_t)BB * KK * DD];   // nb scores (pre-bias)
__device__ float g_sself[(size_t)BB * DD];      // self scores (pre-bias)
__device__ float g_ctx[(size_t)BB * DD];        // context

// ---------------- helpers ------------------------------------------------------
__device__ __forceinline__ float to_tf32(float x) {
    float r;
    asm("cvt.rna.tf32.f32 %0, %1;" : "=f"(r) : "f"(x));
    return r;
}

__device__ __forceinline__ void cp16(void* smem, const void* gmem) {
    uint32_t s = (uint32_t)__cvta_generic_to_shared(smem);
    asm volatile("cp.async.cg.shared.global [%0], [%1], 16;" :: "r"(s), "l"(gmem));
}
__device__ __forceinline__ void cp_commit() {
    asm volatile("cp.async.commit_group;");
}
template <int N> __device__ __forceinline__ void cp_wait() {
    asm volatile("cp.async.wait_group %0;" :: "n"(N));
}

// tf32 mma m16n8k8, D += A*B (accumulate in place)
__device__ __forceinline__ void mma_tf32(float4& d, const uint32_t a[4], const uint32_t b[2]) {
    asm volatile(
        "mma.sync.aligned.m16n8k8.row.col.f32.tf32.tf32.f32 "
        "{%0,%1,%2,%3}, {%4,%5,%6,%7}, {%8,%9}, {%0,%1,%2,%3};"
        : "+f"(d.x), "+f"(d.y), "+f"(d.z), "+f"(d.w)
        : "r"(a[0]), "r"(a[1]), "r"(a[2]), "r"(a[3]), "r"(b[0]), "r"(b[1]));
}

// FFMA-only exp (avoids MUFU bottleneck: 138M exps). Max rel err ~2.4e-6.
__device__ __forceinline__ float fast_exp(float x) {
    float t = x * 1.4426950408889634f;           // x * log2(e)
    int   n = __float2int_rn(t);
    float r = t - (float)n;                      // r in [-0.5, 0.5]
    float p = 0.0013333551f;                     // ln2^5/120
    p = fmaf(p, r, 0.0096181296f);               // ln2^4/24
    p = fmaf(p, r, 0.05550412f);                 // ln2^3/6
    p = fmaf(p, r, 0.2402265f);                  // ln2^2/2
    p = fmaf(p, r, 0.69314718f);                 // ln2
    p = fmaf(p, r, 1.0f);
    return __int_as_float(__float_as_int(p) + (n << 23));
}

// ---------------- kernel 1: LayerNorm all rows ---------------------------------
// 8 warps/CTA, one row per warp. rows [0,BB)=target, [BB, BB+BB*KK)=neighbors.
__global__ __launch_bounds__(256)
void ln_kernel(const float* __restrict__ tgt, const float* __restrict__ nbr,
               const float* __restrict__ ln_scale, const float* __restrict__ ln_bias)
{
    const int r    = blockIdx.x * 8 + (threadIdx.x >> 5);
    const int lane = threadIdx.x & 31;

    const float* src;
    float* dst;
    if (r < BB) { src = tgt + (size_t)r * DD;        dst = g_xnt + (size_t)r * DD; }
    else        { size_t rn = (size_t)(r - BB);
                  src = nbr + rn * DD;               dst = g_xnn + rn * DD; }

    const float4* s4 = (const float4*)src;
    float4 v[8];
    float s = 0.f, q = 0.f;
    #pragma unroll
    for (int j = 0; j < 8; ++j) {
        v[j] = __ldg(s4 + j * 32 + lane);
        s += v[j].x + v[j].y + v[j].z + v[j].w;
        q += v[j].x * v[j].x + v[j].y * v[j].y + v[j].z * v[j].z + v[j].w * v[j].w;
    }
    #pragma unroll
    for (int o = 16; o > 0; o >>= 1) {
        s += __shfl_xor_sync(0xffffffffu, s, o);
        q += __shfl_xor_sync(0xffffffffu, q, o);
    }
    const float mu   = s * (1.0f / 1024.0f);
    const float var  = q * (1.0f / 1024.0f) - mu * mu;
    const float rstd = rsqrtf(var + 1e-5f);

    const float4* sc4 = (const float4*)ln_scale;
    const float4* bi4 = (const float4*)ln_bias;
    #pragma unroll
    for (int j = 0; j < 8; ++j) {
        const float4 sc = __ldg(sc4 + j * 32 + lane);
        const float4 bi = __ldg(bi4 + j * 32 + lane);
        float4 o;
        o.x = (v[j].x - mu) * rstd * sc.x + bi.x;
        o.y = (v[j].y - mu) * rstd * sc.y + bi.y;
        o.z = (v[j].z - mu) * rstd * sc.z + bi.z;
        o.w = (v[j].w - mu) * rstd * sc.w + bi.w;
        *(float4*)&dst[(j * 32 + lane) * 4] = o;
    }
}

// ---------------- kernel 2: 3xTF32 tensor-core GEMM  C = A @ B^T ---------------
// A (M x 1024) row-major fp32, Bw (1024 x 1024) row-major fp32.
// CTA tile 128x128, BK=16, 256 threads = 8 warps (4m x 2n), warp tile 32x64.
// Split-precision in registers: x = hi + lo, hi = tf32_rna(x);
// acc += Ah*Bh + Ah*Bl + Al*Bh  (Al*Bl term ~2^-42, dropped).
__device__ __forceinline__
void gemm_body(const float* __restrict__ A, const float* __restrict__ Bw,
               float* __restrict__ C)
{
    __shared__ float As[2][128 * 20];
    __shared__ float Bs[2][128 * 20];

    const int t    = threadIdx.x;
    const int m0   = blockIdx.y * 128;
    const int e0   = blockIdx.x * 128;
    const int warp = t >> 5, lane = t & 31;
    const int g    = lane >> 2, tig = lane & 3;
    const int wm   = warp >> 1, wn = warp & 1;
    const int mbase = wm * 32, nbase = wn * 64;

    const int srow = t >> 2;           // 0..63
    const int sc4  = (t & 3) << 2;     // 0,4,8,12

    float4 acc[2][8];
    #pragma unroll
    for (int i = 0; i < 2; ++i)
        #pragma unroll
        for (int j = 0; j < 8; ++j) acc[i][j] = make_float4(0.f, 0.f, 0.f, 0.f);

    const float* Agb = A  + (size_t)(m0 + srow) * DD + sc4;
    const float* Bgb = Bw + (size_t)(e0 + srow) * DD + sc4;

    #define STAGE(buf, k0)                                                    \
        do {                                                                  \
            cp16(&As[buf][srow * 20 + sc4],        Agb + (k0));               \
            cp16(&As[buf][(srow + 64) * 20 + sc4], Agb + (k0) + 64 * DD);     \
            cp16(&Bs[buf][srow * 20 + sc4],        Bgb + (k0));               \
            cp16(&Bs[buf][(srow + 64) * 20 + sc4], Bgb + (k0) + 64 * DD);     \
            cp_commit();                                                      \
        } while (0)

    STAGE(0, 0);
    STAGE(1, 16);

    for (int kt = 0; kt < 64; ++kt) {
        if (kt + 1 < 64) cp_wait<1>(); else cp_wait<0>();
        __syncthreads();
        const int buf = kt & 1;
        const float* as = As[buf];
        const float* bs = Bs[buf];
        #pragma unroll
        for (int ks = 0; ks < 16; ks += 8) {
            uint32_t afh[2][4], afl[2][4];
            #pragma unroll
            for (int mt = 0; mt < 2; ++mt) {
                const int r0 = mbase + mt * 16 + g;
                float x0 = as[r0 * 20 + ks + tig];
                float x1 = as[(r0 + 8) * 20 + ks + tig];
                float x2 = as[r0 * 20 + ks + tig + 4];
                float x3 = as[(r0 + 8) * 20 + ks + tig + 4];
                float h0 = to_tf32(x0), h1 = to_tf32(x1);
                float h2 = to_tf32(x2), h3 = to_tf32(x3);
                afh[mt][0] = __float_as_uint(h0);
                afh[mt][1] = __float_as_uint(h1);
                afh[mt][2] = __float_as_uint(h2);
                afh[mt][3] = __float_as_uint(h3);
                afl[mt][0] = __float_as_uint(x0 - h0);
                afl[mt][1] = __float_as_uint(x1 - h1);
                afl[mt][2] = __float_as_uint(x2 - h2);
                afl[mt][3] = __float_as_uint(x3 - h3);
            }
            uint32_t bfh[8][2], bfl[8][2];
            #pragma unroll
            for (int nt = 0; nt < 8; ++nt) {
                const int e = nbase + nt * 8 + g;
                float x0 = bs[e * 20 + ks + tig];
                float x1 = bs[e * 20 + ks + tig + 4];
                float h0 = to_tf32(x0), h1 = to_tf32(x1);
                bfh[nt][0] = __float_as_uint(h0);
                bfh[nt][1] = __float_as_uint(h1);
                bfl[nt][0] = __float_as_uint(x0 - h0);
                bfl[nt][1] = __float_as_uint(x1 - h1);
            }
            #pragma unroll
            for (int mt = 0; mt < 2; ++mt)
                #pragma unroll
                for (int nt = 0; nt < 8; ++nt) {
                    mma_tf32(acc[mt][nt], afh[mt], bfh[nt]);
                    mma_tf32(acc[mt][nt], afh[mt], bfl[nt]);
                    mma_tf32(acc[mt][nt], afl[mt], bfh[nt]);
                }
        }
        __syncthreads();
        if (kt + 2 < 64) STAGE(buf, (kt + 2) * 16);
    }
    #undef STAGE

    #pragma unroll
    for (int mt = 0; mt < 2; ++mt) {
        const int r0 = m0 + mbase + mt * 16 + g;
        #pragma unroll
        for (int nt = 0; nt < 8; ++nt) {
            const int e = e0 + nbase + nt * 8 + 2 * tig;
            const float4 v = acc[mt][nt];
            *(float2*)&C[(size_t)r0 * DD + e]       = make_float2(v.x, v.y);
            *(float2*)&C[(size_t)(r0 + 8) * DD + e] = make_float2(v.z, v.w);
        }
    }
}

__global__ __launch_bounds__(256, 1)
void gemm_nb_kernel(const float* __restrict__ w_nb)
{ gemm_body(g_xnn, w_nb, g_snb); }

__global__ __launch_bounds__(256, 1)
void gemm_self_kernel(const float* __restrict__ w_self)
{ gemm_body(g_xnt, w_self, g_sself); }

// ---------------- kernel 3: epilogue (bias + dist + softmax + thresh + ctx) ----
__global__ __launch_bounds__(256)
void epilogue_kernel(const float* __restrict__ dist, const float* __restrict__ beta_p,
                     const float* __restrict__ b_self, const float* __restrict__ b_nb,
                     float* __restrict__ out_selfw, float* __restrict__ out_nbw)
{
    __shared__ float dw[32];
    const int bx = blockIdx.x;
    const int b  = bx >> 2;
    const int e  = ((bx & 3) << 8) + threadIdx.x;

    if (threadIdx.x < 32) {
        float dv = __ldg(dist + (size_t)b * KK + threadIdx.x);
        dw[threadIdx.x] = expf(dv * (-2.0f / (100.0f + 1e-8f)));
    }
    __syncthreads();

    float acc[33];
    acc[0] = g_sself[(size_t)b * DD + e] + __ldg(b_self + e);
    const float bn = __ldg(b_nb + e);
    #pragma unroll
    for (int k = 0; k < KK; ++k)
        acc[k + 1] = (g_snb[((size_t)b * KK + k) * DD + e] + bn) * dw[k];

    float mx = acc[0];
    #pragma unroll
    for (int m = 1; m < 33; ++m) mx = fmaxf(mx, acc[m]);
    float sum = 0.f;
    #pragma unroll
    for (int m = 0; m < 33; ++m) { acc[m] = fast_exp(acc[m] - mx); sum += acc[m]; }
    const float inv = 1.0f / sum;
    #pragma unroll
    for (int m = 0; m < 33; ++m) {
        const float w = acc[m] * inv;
        acc[m] = (fabsf(w) >= 0.01f) ? w : 0.0f;
    }

    const float beta = __ldg(beta_p);
    out_selfw[(size_t)b * DD + e] = acc[0];
    float ctx = beta * acc[0] * g_xnt[(size_t)b * DD + e];
    float ns  = 0.f;
    #pragma unroll
    for (int k = 0; k < KK; ++k) {
        const float w = acc[k + 1];
        out_nbw[((size_t)b * KK + k) * DD + e] = w;
        ns += w * g_xnn[((size_t)b * KK + k) * DD + e];
    }
    ctx += (1.0f - beta) * ns;
    g_ctx[(size_t)b * DD + e] = ctx;
}

// ---------------- kernel 4: reduced = leaky_relu(ctx @ w_red^T + b_red) --------
__global__ __launch_bounds__(256)
void reduce_kernel(const float* __restrict__ w_red, const float* __restrict__ b_red,
                   float* __restrict__ out_red)
{
    __shared__ float ctx_s[32 * 33];
    __shared__ float w_s[128 * 33];

    const int t  = threadIdx.x;
    const int b0 = blockIdx.x * 32;
    const int tb = t >> 4;
    const int tr = t & 15;

    float acc[2][8];
    #pragma unroll
    for (int i = 0; i < 8; ++i) { acc[0][i] = 0.f; acc[1][i] = 0.f; }

    for (int d0 = 0; d0 < DD; d0 += 32) {
        __syncthreads();
        #pragma unroll
        for (int j = 0; j < 4; ++j) {
            int i = t + 256 * j;
            int row = i >> 5, col = i & 31;
            ctx_s[row * 33 + col] = g_ctx[(size_t)(b0 + row) * DD + d0 + col];
        }
        #pragma unroll
        for (int j = 0; j < 16; ++j) {
            int i = t + 256 * j;
            int row = i >> 5, col = i & 31;
            w_s[row * 33 + col] = __ldg(w_red + (size_t)row * DD + d0 + col);
        }
        __syncthreads();

        #pragma unroll
        for (int dl = 0; dl < 32; ++dl) {
            float c0 = ctx_s[tb * 33 + dl];
            float c1 = ctx_s[(tb + 16) * 33 + dl];
            #pragma unroll
            for (int i = 0; i < 8; ++i) {
                float wv = w_s[(tr + 16 * i) * 33 + dl];
                acc[0][i] += c0 * wv;
                acc[1][i] += c1 * wv;
            }
        }
    }

    #pragma unroll
    for (int i = 0; i < 8; ++i) {
        int r = tr + 16 * i;
        float bias = __ldg(b_red + r);
        float v0 = acc[0][i] + bias;
        float v1 = acc[1][i] + bias;
        v0 = v0 > 0.f ? v0 : 0.01f * v0;
        v1 = v1 > 0.f ? v1 : 0.01f * v1;
        out_red[(size_t)(b0 + tb) * RR + r]      = v0;
        out_red[(size_t)(b0 + tb + 16) * RR + r] = v1;
    }
}

// ---------------------------------------------------------------------------
extern "C" void kernel_launch(void* const* d_in, const int* in_sizes, int n_in,
                              void* d_out, int out_size)
{
    (void)in_sizes; (void)n_in; (void)out_size;

    const float* tgt      = (const float*)d_in[0];
    const float* nbr      = (const float*)d_in[1];
    const float* dist     = (const float*)d_in[2];
    const float* beta_p   = (const float*)d_in[3];
    const float* ln_scale = (const float*)d_in[4];
    const float* ln_bias  = (const float*)d_in[5];
    const float* w_self   = (const float*)d_in[6];
    const float* b_self   = (const float*)d_in[7];
    const float* w_nb     = (const float*)d_in[8];
    const float* b_nb     = (const float*)d_in[9];
    const float* w_red    = (const float*)d_in[10];
    const float* b_red    = (const float*)d_in[11];

    float* out       = (float*)d_out;
    float* out_red   = out;                              // B*R
    float* out_selfw = out + (size_t)BB * RR;            // B*D
    float* out_nbw   = out_selfw + (size_t)BB * DD;      // B*K*D

    ln_kernel<<<(BB * 33) / 8, 256>>>(tgt, nbr, ln_scale, ln_bias);

    gemm_nb_kernel  <<<dim3(DD / 128, (BB * KK) / 128), 256>>>(w_nb);
    gemm_self_kernel<<<dim3(DD / 128, BB / 128),        256>>>(w_self);

    epilogue_kernel<<<BB * 4, 256>>>(dist, beta_p, b_self, b_nb, out_selfw, out_nbw);
    reduce_kernel<<<BB / 32, 256>>>(w_red, b_red, out_red);
}

// round 8
// speedup vs baseline: 3.7175x; 1.5869x over previous
#include <cuda_runtime.h>
#include <cuda_bf16.h>
#include <math.h>
#include <stdint.h>

#define BB 4096
#define KK 32
#define DD 1024
#define RR 128

// ---------------- device scratch (allocation-free rule: __device__ globals) ----
__device__ __nv_bfloat16 g_xnt_hi[(size_t)BB * DD];
__device__ __nv_bfloat16 g_xnt_lo[(size_t)BB * DD];
__device__ __nv_bfloat16 g_xnn_hi[(size_t)BB * KK * DD];
__device__ __nv_bfloat16 g_xnn_lo[(size_t)BB * KK * DD];
__device__ __nv_bfloat16 g_ws_hi[(size_t)DD * DD];
__device__ __nv_bfloat16 g_ws_lo[(size_t)DD * DD];
__device__ __nv_bfloat16 g_wn_hi[(size_t)DD * DD];
__device__ __nv_bfloat16 g_wn_lo[(size_t)DD * DD];
__device__ float g_snb[(size_t)BB * KK * DD];
__device__ float g_sself[(size_t)BB * DD];
__device__ float g_ctx[(size_t)BB * DD];

// ---------------- helpers ------------------------------------------------------
__device__ __forceinline__ void cp16(void* smem, const void* gmem) {
    uint32_t s = (uint32_t)__cvta_generic_to_shared(smem);
    asm volatile("cp.async.cg.shared.global [%0], [%1], 16;" :: "r"(s), "l"(gmem));
}
__device__ __forceinline__ void cp_commit() {
    asm volatile("cp.async.commit_group;");
}
template <int N> __device__ __forceinline__ void cp_wait() {
    asm volatile("cp.async.wait_group %0;" :: "n"(N));
}

// bf16 mma m16n8k16, D += A*B (accumulate in place)
__device__ __forceinline__ void mma_bf16(float4& d, const uint32_t a[4], const uint32_t b[2]) {
    asm volatile(
        "mma.sync.aligned.m16n8k16.row.col.f32.bf16.bf16.f32 "
        "{%0,%1,%2,%3}, {%4,%5,%6,%7}, {%8,%9}, {%0,%1,%2,%3};"
        : "+f"(d.x), "+f"(d.y), "+f"(d.z), "+f"(d.w)
        : "r"(a[0]), "r"(a[1]), "r"(a[2]), "r"(a[3]), "r"(b[0]), "r"(b[1]));
}

// FFMA-only exp. Max rel err ~2.4e-6.
__device__ __forceinline__ float fast_exp(float x) {
    float t = x * 1.4426950408889634f;
    int   n = __float2int_rn(t);
    float r = t - (float)n;
    float p = 0.0013333551f;
    p = fmaf(p, r, 0.0096181296f);
    p = fmaf(p, r, 0.05550412f);
    p = fmaf(p, r, 0.2402265f);
    p = fmaf(p, r, 0.69314718f);
    p = fmaf(p, r, 1.0f);
    return __int_as_float(__float_as_int(p) + (n << 23));
}

// ---------------- kernel 0: weight split fp32 -> bf16 hi/lo --------------------
__global__ __launch_bounds__(256)
void wprep_kernel(const float* __restrict__ ws, const float* __restrict__ wn) {
    int i = blockIdx.x * 256 + threadIdx.x;      // grid 4096 -> DD*DD threads
    float a = __ldg(ws + i);
    __nv_bfloat16 h = __float2bfloat16(a);
    g_ws_hi[i] = h;
    g_ws_lo[i] = __float2bfloat16(a - __bfloat162float(h));
    float b = __ldg(wn + i);
    __nv_bfloat16 h2 = __float2bfloat16(b);
    g_wn_hi[i] = h2;
    g_wn_lo[i] = __float2bfloat16(b - __bfloat162float(h2));
}

// ---------------- kernel 1: LayerNorm -> bf16 hi/lo ----------------------------
// 8 warps/CTA, one row per warp. rows [0,BB)=target, [BB, BB+BB*KK)=neighbors.
__global__ __launch_bounds__(256)
void ln_kernel(const float* __restrict__ tgt, const float* __restrict__ nbr,
               const float* __restrict__ ln_scale, const float* __restrict__ ln_bias)
{
    const int r    = blockIdx.x * 8 + (threadIdx.x >> 5);
    const int lane = threadIdx.x & 31;

    const float* src;
    __nv_bfloat16 *dh, *dl;
    if (r < BB) {
        src = tgt + (size_t)r * DD;
        dh = g_xnt_hi + (size_t)r * DD; dl = g_xnt_lo + (size_t)r * DD;
    } else {
        size_t rn = (size_t)(r - BB);
        src = nbr + rn * DD;
        dh = g_xnn_hi + rn * DD; dl = g_xnn_lo + rn * DD;
    }

    const float4* s4 = (const float4*)src;
    float4 v[8];
    float s = 0.f, q = 0.f;
    #pragma unroll
    for (int j = 0; j < 8; ++j) {
        v[j] = __ldg(s4 + j * 32 + lane);
        s += v[j].x + v[j].y + v[j].z + v[j].w;
        q += v[j].x * v[j].x + v[j].y * v[j].y + v[j].z * v[j].z + v[j].w * v[j].w;
    }
    #pragma unroll
    for (int o = 16; o > 0; o >>= 1) {
        s += __shfl_xor_sync(0xffffffffu, s, o);
        q += __shfl_xor_sync(0xffffffffu, q, o);
    }
    const float mu   = s * (1.0f / 1024.0f);
    const float var  = q * (1.0f / 1024.0f) - mu * mu;
    const float rstd = rsqrtf(var + 1e-5f);

    const float4* sc4 = (const float4*)ln_scale;
    const float4* bi4 = (const float4*)ln_bias;
    #pragma unroll
    for (int j = 0; j < 8; ++j) {
        const float4 sc = __ldg(sc4 + j * 32 + lane);
        const float4 bi = __ldg(bi4 + j * 32 + lane);
        float o0 = (v[j].x - mu) * rstd * sc.x + bi.x;
        float o1 = (v[j].y - mu) * rstd * sc.y + bi.y;
        float o2 = (v[j].z - mu) * rstd * sc.z + bi.z;
        float o3 = (v[j].w - mu) * rstd * sc.w + bi.w;
        __nv_bfloat16 h0 = __float2bfloat16(o0), h1 = __float2bfloat16(o1);
        __nv_bfloat16 h2 = __float2bfloat16(o2), h3 = __float2bfloat16(o3);
        __nv_bfloat16 l0 = __float2bfloat16(o0 - __bfloat162float(h0));
        __nv_bfloat16 l1 = __float2bfloat16(o1 - __bfloat162float(h1));
        __nv_bfloat16 l2 = __float2bfloat16(o2 - __bfloat162float(h2));
        __nv_bfloat16 l3 = __float2bfloat16(o3 - __bfloat162float(h3));
        const int d = (j * 32 + lane) * 4;
        uint2 hv, lv;
        hv.x = (uint32_t)__bfloat16_as_ushort(h0) | ((uint32_t)__bfloat16_as_ushort(h1) << 16);
        hv.y = (uint32_t)__bfloat16_as_ushort(h2) | ((uint32_t)__bfloat16_as_ushort(h3) << 16);
        lv.x = (uint32_t)__bfloat16_as_ushort(l0) | ((uint32_t)__bfloat16_as_ushort(l1) << 16);
        lv.y = (uint32_t)__bfloat16_as_ushort(l2) | ((uint32_t)__bfloat16_as_ushort(l3) << 16);
        *(uint2*)&dh[d] = hv;
        *(uint2*)&dl[d] = lv;
    }
}

// ---------------- kernel 2: 3xBF16 HMMA GEMM  C = A @ B^T ----------------------
// A (M x 1024), Bw (1024 x 1024) row-major, both as bf16 hi/lo pairs.
// CTA tile 128x128, K-slab 32 bf16, 256 threads = 8 warps (4m x 2n), warp 32x64.
// acc += Ah*Bh + Ah*Bl + Al*Bh via mma.m16n8k16 (Al*Bl ~2^-16/prod, dropped).
//
// SMEM row = 32 bf16 data + pad = 20 uint32 (80B). Fragment LDS banks:
// (r*20 + tig) mod 32 -> r spans {0,4,...,28}, +tig -> all 32 distinct.
#define ROWU 20
#define ARR_B (128 * ROWU * 4)                  // 10240 bytes per array
#define STAGE_B (4 * ARR_B)                     // 40960 per stage
#define GEMM_SMEM (2 * STAGE_B)                 // 81920

__device__ __forceinline__
void gemm_body(const __nv_bfloat16* __restrict__ Ah, const __nv_bfloat16* __restrict__ Al,
               const __nv_bfloat16* __restrict__ Bh, const __nv_bfloat16* __restrict__ Bl,
               float* __restrict__ C)
{
    extern __shared__ char smem[];

    const int t    = threadIdx.x;
    const int m0   = blockIdx.y * 128;
    const int e0   = blockIdx.x * 128;
    const int warp = t >> 5, lane = t & 31;
    const int g    = lane >> 2, tig = lane & 3;
    const int wm   = warp >> 1, wn = warp & 1;
    const int mbase = wm * 32, nbase = wn * 64;

    float4 acc[2][8];
    #pragma unroll
    for (int i = 0; i < 2; ++i)
        #pragma unroll
        for (int j = 0; j < 8; ++j) acc[i][j] = make_float4(0.f, 0.f, 0.f, 0.f);

    // stage slab (32 k) into buffer: 4 arrays x 512 16B-chunks = 8 cp16/thread
    #define STAGE(slab, buf)                                                     \
        do {                                                                     \
            const int k0 = (slab) * 32;                                          \
            char* bufp = smem + (buf) * STAGE_B;                                 \
            _Pragma("unroll")                                                    \
            for (int j = 0; j < 8; ++j) {                                        \
                int i   = t + 256 * j;                                           \
                int arr = i >> 9;                                                \
                int idx = i & 511;                                               \
                int row = idx >> 2, c = idx & 3;                                 \
                const __nv_bfloat16* src =                                       \
                    (arr == 0 ? Ah : arr == 1 ? Al : arr == 2 ? Bh : Bl)         \
                    + (size_t)((arr < 2 ? m0 : e0) + row) * DD + k0 + c * 8;     \
                cp16(bufp + arr * ARR_B + row * 80 + c * 16, src);               \
            }                                                                    \
            cp_commit();                                                         \
        } while (0)

    STAGE(0, 0);
    STAGE(1, 1);

    for (int kt = 0; kt < 32; ++kt) {
        if (kt + 1 < 32) cp_wait<1>(); else cp_wait<0>();
        __syncthreads();
        const int buf = kt & 1;
        const uint32_t* sAh = (const uint32_t*)(smem + buf * STAGE_B);
        const uint32_t* sAl = (const uint32_t*)(smem + buf * STAGE_B + ARR_B);
        const uint32_t* sBh = (const uint32_t*)(smem + buf * STAGE_B + 2 * ARR_B);
        const uint32_t* sBl = (const uint32_t*)(smem + buf * STAGE_B + 3 * ARR_B);

        #pragma unroll
        for (int s2 = 0; s2 < 2; ++s2) {        // two k16 steps per slab
            const int ko = s2 * 8;
            uint32_t ah[2][4], al[2][4];
            #pragma unroll
            for (int mt = 0; mt < 2; ++mt) {
                const int r0 = (mbase + mt * 16 + g) * ROWU + ko + tig;
                const int r1 = r0 + 8 * ROWU;
                ah[mt][0] = sAh[r0];     ah[mt][1] = sAh[r1];
                ah[mt][2] = sAh[r0 + 4]; ah[mt][3] = sAh[r1 + 4];
                al[mt][0] = sAl[r0];     al[mt][1] = sAl[r1];
                al[mt][2] = sAl[r0 + 4]; al[mt][3] = sAl[r1 + 4];
            }
            uint32_t bh[8][2], bl[8][2];
            #pragma unroll
            for (int nt = 0; nt < 8; ++nt) {
                const int e = (nbase + nt * 8 + g) * ROWU + ko + tig;
                bh[nt][0] = sBh[e]; bh[nt][1] = sBh[e + 4];
                bl[nt][0] = sBl[e]; bl[nt][1] = sBl[e + 4];
            }
            #pragma unroll
            for (int mt = 0; mt < 2; ++mt)
                #pragma unroll
                for (int nt = 0; nt < 8; ++nt) {
                    mma_bf16(acc[mt][nt], ah[mt], bh[nt]);
                    mma_bf16(acc[mt][nt], ah[mt], bl[nt]);
                    mma_bf16(acc[mt][nt], al[mt], bh[nt]);
                }
        }
        __syncthreads();
        if (kt + 2 < 32) STAGE(kt + 2, buf);
    }
    #undef STAGE

    #pragma unroll
    for (int mt = 0; mt < 2; ++mt) {
        const int r0 = m0 + mbase + mt * 16 + g;
        #pragma unroll
        for (int nt = 0; nt < 8; ++nt) {
            const int e = e0 + nbase + nt * 8 + 2 * tig;
            const float4 v = acc[mt][nt];
            *(float2*)&C[(size_t)r0 * DD + e]       = make_float2(v.x, v.y);
            *(float2*)&C[(size_t)(r0 + 8) * DD + e] = make_float2(v.z, v.w);
        }
    }
}

__global__ __launch_bounds__(256, 1)
void gemm_nb_kernel() {
    gemm_body(g_xnn_hi, g_xnn_lo, g_wn_hi, g_wn_lo, g_snb);
}
__global__ __launch_bounds__(256, 1)
void gemm_self_kernel() {
    gemm_body(g_xnt_hi, g_xnt_lo, g_ws_hi, g_ws_lo, g_sself);
}

// ---------------- kernel 3: epilogue -------------------------------------------
__global__ __launch_bounds__(256)
void epilogue_kernel(const float* __restrict__ dist, const float* __restrict__ beta_p,
                     const float* __restrict__ b_self, const float* __restrict__ b_nb,
                     float* __restrict__ out_selfw, float* __restrict__ out_nbw)
{
    __shared__ float dw[32];
    const int bx = blockIdx.x;
    const int b  = bx >> 2;
    const int e  = ((bx & 3) << 8) + threadIdx.x;

    if (threadIdx.x < 32) {
        float dv = __ldg(dist + (size_t)b * KK + threadIdx.x);
        dw[threadIdx.x] = expf(dv * (-2.0f / (100.0f + 1e-8f)));
    }
    __syncthreads();

    float acc[33];
    acc[0] = g_sself[(size_t)b * DD + e] + __ldg(b_self + e);
    const float bn = __ldg(b_nb + e);
    #pragma unroll
    for (int k = 0; k < KK; ++k)
        acc[k + 1] = (g_snb[((size_t)b * KK + k) * DD + e] + bn) * dw[k];

    float mx = acc[0];
    #pragma unroll
    for (int m = 1; m < 33; ++m) mx = fmaxf(mx, acc[m]);
    float sum = 0.f;
    #pragma unroll
    for (int m = 0; m < 33; ++m) { acc[m] = fast_exp(acc[m] - mx); sum += acc[m]; }
    const float inv = 1.0f / sum;
    #pragma unroll
    for (int m = 0; m < 33; ++m) {
        const float w = acc[m] * inv;
        acc[m] = (fabsf(w) >= 0.01f) ? w : 0.0f;
    }

    const float beta = __ldg(beta_p);
    out_selfw[(size_t)b * DD + e] = acc[0];
    const size_t ti = (size_t)b * DD + e;
    const float xnt = __bfloat162float(g_xnt_hi[ti]) + __bfloat162float(g_xnt_lo[ti]);
    float ctx = beta * acc[0] * xnt;
    float ns  = 0.f;
    #pragma unroll
    for (int k = 0; k < KK; ++k) {
        const float w = acc[k + 1];
        const size_t ni = ((size_t)b * KK + k) * DD + e;
        out_nbw[ni] = w;
        const float xnn = __bfloat162float(g_xnn_hi[ni]) + __bfloat162float(g_xnn_lo[ni]);
        ns += w * xnn;
    }
    ctx += (1.0f - beta) * ns;
    g_ctx[(size_t)b * DD + e] = ctx;
}

// ---------------- kernel 4: reduced = leaky_relu(ctx @ w_red^T + b_red) --------
__global__ __launch_bounds__(256)
void reduce_kernel(const float* __restrict__ w_red, const float* __restrict__ b_red,
                   float* __restrict__ out_red)
{
    __shared__ float ctx_s[32 * 33];
    __shared__ float w_s[128 * 33];

    const int t  = threadIdx.x;
    const int b0 = blockIdx.x * 32;
    const int tb = t >> 4;
    const int tr = t & 15;

    float acc[2][8];
    #pragma unroll
    for (int i = 0; i < 8; ++i) { acc[0][i] = 0.f; acc[1][i] = 0.f; }

    for (int d0 = 0; d0 < DD; d0 += 32) {
        __syncthreads();
        #pragma unroll
        for (int j = 0; j < 4; ++j) {
            int i = t + 256 * j;
            int row = i >> 5, col = i & 31;
            ctx_s[row * 33 + col] = g_ctx[(size_t)(b0 + row) * DD + d0 + col];
        }
        #pragma unroll
        for (int j = 0; j < 16; ++j) {
            int i = t + 256 * j;
            int row = i >> 5, col = i & 31;
            w_s[row * 33 + col] = __ldg(w_red + (size_t)row * DD + d0 + col);
        }
        __syncthreads();

        #pragma unroll
        for (int dl = 0; dl < 32; ++dl) {
            float c0 = ctx_s[tb * 33 + dl];
            float c1 = ctx_s[(tb + 16) * 33 + dl];
            #pragma unroll
            for (int i = 0; i < 8; ++i) {
                float wv = w_s[(tr + 16 * i) * 33 + dl];
                acc[0][i] += c0 * wv;
                acc[1][i] += c1 * wv;
            }
        }
    }

    #pragma unroll
    for (int i = 0; i < 8; ++i) {
        int r = tr + 16 * i;
        float bias = __ldg(b_red + r);
        float v0 = acc[0][i] + bias;
        float v1 = acc[1][i] + bias;
        v0 = v0 > 0.f ? v0 : 0.01f * v0;
        v1 = v1 > 0.f ? v1 : 0.01f * v1;
        out_red[(size_t)(b0 + tb) * RR + r]      = v0;
        out_red[(size_t)(b0 + tb + 16) * RR + r] = v1;
    }
}

// ---------------------------------------------------------------------------
extern "C" void kernel_launch(void* const* d_in, const int* in_sizes, int n_in,
                              void* d_out, int out_size)
{
    (void)in_sizes; (void)n_in; (void)out_size;

    const float* tgt      = (const float*)d_in[0];
    const float* nbr      = (const float*)d_in[1];
    const float* dist     = (const float*)d_in[2];
    const float* beta_p   = (const float*)d_in[3];
    const float* ln_scale = (const float*)d_in[4];
    const float* ln_bias  = (const float*)d_in[5];
    const float* w_self   = (const float*)d_in[6];
    const float* b_self   = (const float*)d_in[7];
    const float* w_nb     = (const float*)d_in[8];
    const float* b_nb     = (const float*)d_in[9];
    const float* w_red    = (const float*)d_in[10];
    const float* b_red    = (const float*)d_in[11];

    float* out       = (float*)d_out;
    float* out_red   = out;                              // B*R
    float* out_selfw = out + (size_t)BB * RR;            // B*D
    float* out_nbw   = out_selfw + (size_t)BB * DD;      // B*K*D

    cudaFuncSetAttribute(gemm_nb_kernel,
                         cudaFuncAttributeMaxDynamicSharedMemorySize, GEMM_SMEM);
    cudaFuncSetAttribute(gemm_self_kernel,
                         cudaFuncAttributeMaxDynamicSharedMemorySize, GEMM_SMEM);

    wprep_kernel<<<DD * DD / 256, 256>>>(w_self, w_nb);
    ln_kernel<<<(BB * 33) / 8, 256>>>(tgt, nbr, ln_scale, ln_bias);

    gemm_nb_kernel  <<<dim3(DD / 128, (BB * KK) / 128), 256, GEMM_SMEM>>>();
    gemm_self_kernel<<<dim3(DD / 128, BB / 128),        256, GEMM_SMEM>>>();

    epilogue_kernel<<<BB * 4, 256>>>(dist, beta_p, b_self, b_nb, out_selfw, out_nbw);
    reduce_kernel<<<BB / 32, 256>>>(w_red, b_red, out_red);
}

// round 9
// speedup vs baseline: 4.0400x; 1.0868x over previous
#include <cuda_runtime.h>
#include <cuda_bf16.h>
#include <math.h>
#include <stdint.h>

#define BB 4096
#define KK 32
#define DD 1024
#define RR 128

// ---------------- device scratch (allocation-free rule: __device__ globals) ----
__device__ __nv_bfloat16 g_xnt_hi[(size_t)BB * DD];
__device__ __nv_bfloat16 g_xnt_lo[(size_t)BB * DD];
__device__ __nv_bfloat16 g_xnn_hi[(size_t)BB * KK * DD];
__device__ __nv_bfloat16 g_xnn_lo[(size_t)BB * KK * DD];
__device__ __nv_bfloat16 g_ws_hi[(size_t)DD * DD];
__device__ __nv_bfloat16 g_ws_lo[(size_t)DD * DD];
__device__ __nv_bfloat16 g_wn_hi[(size_t)DD * DD];
__device__ __nv_bfloat16 g_wn_lo[(size_t)DD * DD];
__device__ float g_snb[(size_t)BB * KK * DD];
__device__ float g_sself[(size_t)BB * DD];
__device__ float g_ctx[(size_t)BB * DD];

// ---------------- helpers ------------------------------------------------------
__device__ __forceinline__ void cp16(void* smem, const void* gmem) {
    uint32_t s = (uint32_t)__cvta_generic_to_shared(smem);
    asm volatile("cp.async.cg.shared.global [%0], [%1], 16;" :: "r"(s), "l"(gmem));
}
__device__ __forceinline__ void cp_commit() {
    asm volatile("cp.async.commit_group;");
}
template <int N> __device__ __forceinline__ void cp_wait() {
    asm volatile("cp.async.wait_group %0;" :: "n"(N));
}

// bf16 mma m16n8k16, D += A*B (accumulate in place)
__device__ __forceinline__ void mma_bf16(float4& d, const uint32_t a[4], const uint32_t b[2]) {
    asm volatile(
        "mma.sync.aligned.m16n8k16.row.col.f32.bf16.bf16.f32 "
        "{%0,%1,%2,%3}, {%4,%5,%6,%7}, {%8,%9}, {%0,%1,%2,%3};"
        : "+f"(d.x), "+f"(d.y), "+f"(d.z), "+f"(d.w)
        : "r"(a[0]), "r"(a[1]), "r"(a[2]), "r"(a[3]), "r"(b[0]), "r"(b[1]));
}

// FFMA-only exp. Max rel err ~2.4e-6.
__device__ __forceinline__ float fast_exp(float x) {
    float t = x * 1.4426950408889634f;
    int   n = __float2int_rn(t);
    float r = t - (float)n;
    float p = 0.0013333551f;
    p = fmaf(p, r, 0.0096181296f);
    p = fmaf(p, r, 0.05550412f);
    p = fmaf(p, r, 0.2402265f);
    p = fmaf(p, r, 0.69314718f);
    p = fmaf(p, r, 1.0f);
    return __int_as_float(__float_as_int(p) + (n << 23));
}

// ---------------- kernel 0: weight split fp32 -> bf16 hi/lo --------------------
__global__ __launch_bounds__(256)
void wprep_kernel(const float* __restrict__ ws, const float* __restrict__ wn) {
    int i = blockIdx.x * 256 + threadIdx.x;      // grid 4096 -> DD*DD threads
    float a = __ldg(ws + i);
    __nv_bfloat16 h = __float2bfloat16(a);
    g_ws_hi[i] = h;
    g_ws_lo[i] = __float2bfloat16(a - __bfloat162float(h));
    float b = __ldg(wn + i);
    __nv_bfloat16 h2 = __float2bfloat16(b);
    g_wn_hi[i] = h2;
    g_wn_lo[i] = __float2bfloat16(b - __bfloat162float(h2));
}

// ---------------- kernel 1: LayerNorm -> bf16 hi/lo ----------------------------
__global__ __launch_bounds__(256)
void ln_kernel(const float* __restrict__ tgt, const float* __restrict__ nbr,
               const float* __restrict__ ln_scale, const float* __restrict__ ln_bias)
{
    const int r    = blockIdx.x * 8 + (threadIdx.x >> 5);
    const int lane = threadIdx.x & 31;

    const float* src;
    __nv_bfloat16 *dh, *dl;
    if (r < BB) {
        src = tgt + (size_t)r * DD;
        dh = g_xnt_hi + (size_t)r * DD; dl = g_xnt_lo + (size_t)r * DD;
    } else {
        size_t rn = (size_t)(r - BB);
        src = nbr + rn * DD;
        dh = g_xnn_hi + rn * DD; dl = g_xnn_lo + rn * DD;
    }

    const float4* s4 = (const float4*)src;
    float4 v[8];
    float s = 0.f, q = 0.f;
    #pragma unroll
    for (int j = 0; j < 8; ++j) {
        v[j] = __ldg(s4 + j * 32 + lane);
        s += v[j].x + v[j].y + v[j].z + v[j].w;
        q += v[j].x * v[j].x + v[j].y * v[j].y + v[j].z * v[j].z + v[j].w * v[j].w;
    }
    #pragma unroll
    for (int o = 16; o > 0; o >>= 1) {
        s += __shfl_xor_sync(0xffffffffu, s, o);
        q += __shfl_xor_sync(0xffffffffu, q, o);
    }
    const float mu   = s * (1.0f / 1024.0f);
    const float var  = q * (1.0f / 1024.0f) - mu * mu;
    const float rstd = rsqrtf(var + 1e-5f);

    const float4* sc4 = (const float4*)ln_scale;
    const float4* bi4 = (const float4*)ln_bias;
    #pragma unroll
    for (int j = 0; j < 8; ++j) {
        const float4 sc = __ldg(sc4 + j * 32 + lane);
        const float4 bi = __ldg(bi4 + j * 32 + lane);
        float o0 = (v[j].x - mu) * rstd * sc.x + bi.x;
        float o1 = (v[j].y - mu) * rstd * sc.y + bi.y;
        float o2 = (v[j].z - mu) * rstd * sc.z + bi.z;
        float o3 = (v[j].w - mu) * rstd * sc.w + bi.w;
        __nv_bfloat16 h0 = __float2bfloat16(o0), h1 = __float2bfloat16(o1);
        __nv_bfloat16 h2 = __float2bfloat16(o2), h3 = __float2bfloat16(o3);
        __nv_bfloat16 l0 = __float2bfloat16(o0 - __bfloat162float(h0));
        __nv_bfloat16 l1 = __float2bfloat16(o1 - __bfloat162float(h1));
        __nv_bfloat16 l2 = __float2bfloat16(o2 - __bfloat162float(h2));
        __nv_bfloat16 l3 = __float2bfloat16(o3 - __bfloat162float(h3));
        const int d = (j * 32 + lane) * 4;
        uint2 hv, lv;
        hv.x = (uint32_t)__bfloat16_as_ushort(h0) | ((uint32_t)__bfloat16_as_ushort(h1) << 16);
        hv.y = (uint32_t)__bfloat16_as_ushort(h2) | ((uint32_t)__bfloat16_as_ushort(h3) << 16);
        lv.x = (uint32_t)__bfloat16_as_ushort(l0) | ((uint32_t)__bfloat16_as_ushort(l1) << 16);
        lv.y = (uint32_t)__bfloat16_as_ushort(l2) | ((uint32_t)__bfloat16_as_ushort(l3) << 16);
        *(uint2*)&dh[d] = hv;
        *(uint2*)&dl[d] = lv;
    }
}

// ---------------- kernel 2: merged 3xBF16 HMMA GEMM ----------------------------
// Row-space concat: y-tiles [0,1024) = neighbor rows (A = g_xnn, B = w_nb,
// C = g_snb); y-tiles [1024,1056) = target rows (A = g_xnt, B = w_self,
// C = g_sself). CTA tile 128x128, K-slab 32 bf16, double-buffered cp.async.
// 3 terms: acc += Ah*Bh + Ah*Bl + Al*Bh via mma.m16n8k16.
// __launch_bounds__(256,2): regs<=128 -> 2 CTAs/SM (smem 2x80KB fits 228KB).
#define ROWU 20
#define ARR_B (128 * ROWU * 4)                  // 10240 bytes per array
#define STAGE_B (4 * ARR_B)                     // 40960 per stage
#define GEMM_SMEM (2 * STAGE_B)                 // 81920

__global__ __launch_bounds__(256, 2)
void gemm_all_kernel()
{
    extern __shared__ char smem[];

    const int ty = blockIdx.y;
    const __nv_bfloat16 *Ah, *Al, *Bh, *Bl;
    float* C;
    int m0;
    if (ty < (BB * KK) / 128) {
        Ah = g_xnn_hi; Al = g_xnn_lo; Bh = g_wn_hi; Bl = g_wn_lo;
        C = g_snb; m0 = ty * 128;
    } else {
        Ah = g_xnt_hi; Al = g_xnt_lo; Bh = g_ws_hi; Bl = g_ws_lo;
        C = g_sself; m0 = (ty - (BB * KK) / 128) * 128;
    }

    const int t    = threadIdx.x;
    const int e0   = blockIdx.x * 128;
    const int warp = t >> 5, lane = t & 31;
    const int g    = lane >> 2, tig = lane & 3;
    const int wm   = warp >> 1, wnb = warp & 1;
    const int mbase = wm * 32, nbase = wnb * 64;

    float4 acc[2][8];
    #pragma unroll
    for (int i = 0; i < 2; ++i)
        #pragma unroll
        for (int j = 0; j < 8; ++j) acc[i][j] = make_float4(0.f, 0.f, 0.f, 0.f);

    // stage slab (32 k) into buffer: 4 arrays x 512 16B-chunks = 8 cp16/thread
    #define STAGE(slab, buf)                                                     \
        do {                                                                     \
            const int k0 = (slab) * 32;                                          \
            char* bufp = smem + (buf) * STAGE_B;                                 \
            _Pragma("unroll")                                                    \
            for (int j = 0; j < 8; ++j) {                                        \
                int i   = t + 256 * j;                                           \
                int arr = i >> 9;                                                \
                int idx = i & 511;                                               \
                int row = idx >> 2, c = idx & 3;                                 \
                const __nv_bfloat16* src =                                       \
                    (arr == 0 ? Ah : arr == 1 ? Al : arr == 2 ? Bh : Bl)         \
                    + (size_t)((arr < 2 ? m0 : e0) + row) * DD + k0 + c * 8;     \
                cp16(bufp + arr * ARR_B + row * 80 + c * 16, src);               \
            }                                                                    \
            cp_commit();                                                         \
        } while (0)

    STAGE(0, 0);
    STAGE(1, 1);

    for (int kt = 0; kt < 32; ++kt) {
        if (kt + 1 < 32) cp_wait<1>(); else cp_wait<0>();
        __syncthreads();
        const int buf = kt & 1;
        const uint32_t* sAh = (const uint32_t*)(smem + buf * STAGE_B);
        const uint32_t* sAl = (const uint32_t*)(smem + buf * STAGE_B + ARR_B);
        const uint32_t* sBh = (const uint32_t*)(smem + buf * STAGE_B + 2 * ARR_B);
        const uint32_t* sBl = (const uint32_t*)(smem + buf * STAGE_B + 3 * ARR_B);

        #pragma unroll
        for (int s2 = 0; s2 < 2; ++s2) {        // two k16 steps per slab
            const int ko = s2 * 8;
            uint32_t ah[2][4], al[2][4];
            #pragma unroll
            for (int mt = 0; mt < 2; ++mt) {
                const int r0 = (mbase + mt * 16 + g) * ROWU + ko + tig;
                const int r1 = r0 + 8 * ROWU;
                ah[mt][0] = sAh[r0];     ah[mt][1] = sAh[r1];
                ah[mt][2] = sAh[r0 + 4]; ah[mt][3] = sAh[r1 + 4];
                al[mt][0] = sAl[r0];     al[mt][1] = sAl[r1];
                al[mt][2] = sAl[r0 + 4]; al[mt][3] = sAl[r1 + 4];
            }
            // B fragments loaded per-nt (4 live regs) to fit 128-reg budget
            #pragma unroll
            for (int nt = 0; nt < 8; ++nt) {
                const int e = (nbase + nt * 8 + g) * ROWU + ko + tig;
                uint32_t bh[2], bl[2];
                bh[0] = sBh[e]; bh[1] = sBh[e + 4];
                bl[0] = sBl[e]; bl[1] = sBl[e + 4];
                mma_bf16(acc[0][nt], ah[0], bh);
                mma_bf16(acc[0][nt], ah[0], bl);
                mma_bf16(acc[0][nt], al[0], bh);
                mma_bf16(acc[1][nt], ah[1], bh);
                mma_bf16(acc[1][nt], ah[1], bl);
                mma_bf16(acc[1][nt], al[1], bh);
            }
        }
        __syncthreads();
        if (kt + 2 < 32) STAGE(kt + 2, buf);
    }
    #undef STAGE

    #pragma unroll
    for (int mt = 0; mt < 2; ++mt) {
        const int r0 = m0 + mbase + mt * 16 + g;
        #pragma unroll
        for (int nt = 0; nt < 8; ++nt) {
            const int e = e0 + nbase + nt * 8 + 2 * tig;
            const float4 v = acc[mt][nt];
            *(float2*)&C[(size_t)r0 * DD + e]       = make_float2(v.x, v.y);
            *(float2*)&C[(size_t)(r0 + 8) * DD + e] = make_float2(v.z, v.w);
        }
    }
}

// ---------------- kernel 3: epilogue -------------------------------------------
__global__ __launch_bounds__(256)
void epilogue_kernel(const float* __restrict__ dist, const float* __restrict__ beta_p,
                     const float* __restrict__ b_self, const float* __restrict__ b_nb,
                     float* __restrict__ out_selfw, float* __restrict__ out_nbw)
{
    __shared__ float dw[32];
    const int bx = blockIdx.x;
    const int b  = bx >> 2;
    const int e  = ((bx & 3) << 8) + threadIdx.x;

    if (threadIdx.x < 32) {
        float dv = __ldg(dist + (size_t)b * KK + threadIdx.x);
        dw[threadIdx.x] = expf(dv * (-2.0f / (100.0f + 1e-8f)));
    }
    __syncthreads();

    float acc[33];
    acc[0] = g_sself[(size_t)b * DD + e] + __ldg(b_self + e);
    const float bn = __ldg(b_nb + e);
    #pragma unroll
    for (int k = 0; k < KK; ++k)
        acc[k + 1] = (g_snb[((size_t)b * KK + k) * DD + e] + bn) * dw[k];

    float mx = acc[0];
    #pragma unroll
    for (int m = 1; m < 33; ++m) mx = fmaxf(mx, acc[m]);
    float sum = 0.f;
    #pragma unroll
    for (int m = 0; m < 33; ++m) { acc[m] = fast_exp(acc[m] - mx); sum += acc[m]; }
    const float inv = 1.0f / sum;
    #pragma unroll
    for (int m = 0; m < 33; ++m) {
        const float w = acc[m] * inv;
        acc[m] = (fabsf(w) >= 0.01f) ? w : 0.0f;
    }

    const float beta = __ldg(beta_p);
    out_selfw[(size_t)b * DD + e] = acc[0];
    const size_t ti = (size_t)b * DD + e;
    const float xnt = __bfloat162float(g_xnt_hi[ti]) + __bfloat162float(g_xnt_lo[ti]);
    float ctx = beta * acc[0] * xnt;
    float ns  = 0.f;
    #pragma unroll
    for (int k = 0; k < KK; ++k) {
        const float w = acc[k + 1];
        const size_t ni = ((size_t)b * KK + k) * DD + e;
        out_nbw[ni] = w;
        const float xnn = __bfloat162float(g_xnn_hi[ni]) + __bfloat162float(g_xnn_lo[ni]);
        ns += w * xnn;
    }
    ctx += (1.0f - beta) * ns;
    g_ctx[(size_t)b * DD + e] = ctx;
}

// ---------------- kernel 4: reduced = leaky_relu(ctx @ w_red^T + b_red) --------
__global__ __launch_bounds__(256)
void reduce_kernel(const float* __restrict__ w_red, const float* __restrict__ b_red,
                   float* __restrict__ out_red)
{
    __shared__ float ctx_s[32 * 33];
    __shared__ float w_s[128 * 33];

    const int t  = threadIdx.x;
    const int b0 = blockIdx.x * 32;
    const int tb = t >> 4;
    const int tr = t & 15;

    float acc[2][8];
    #pragma unroll
    for (int i = 0; i < 8; ++i) { acc[0][i] = 0.f; acc[1][i] = 0.f; }

    for (int d0 = 0; d0 < DD; d0 += 32) {
        __syncthreads();
        #pragma unroll
        for (int j = 0; j < 4; ++j) {
            int i = t + 256 * j;
            int row = i >> 5, col = i & 31;
            ctx_s[row * 33 + col] = g_ctx[(size_t)(b0 + row) * DD + d0 + col];
        }
        #pragma unroll
        for (int j = 0; j < 16; ++j) {
            int i = t + 256 * j;
            int row = i >> 5, col = i & 31;
            w_s[row * 33 + col] = __ldg(w_red + (size_t)row * DD + d0 + col);
        }
        __syncthreads();

        #pragma unroll
        for (int dl = 0; dl < 32; ++dl) {
            float c0 = ctx_s[tb * 33 + dl];
            float c1 = ctx_s[(tb + 16) * 33 + dl];
            #pragma unroll
            for (int i = 0; i < 8; ++i) {
                float wv = w_s[(tr + 16 * i) * 33 + dl];
                acc[0][i] += c0 * wv;
                acc[1][i] += c1 * wv;
            }
        }
    }

    #pragma unroll
    for (int i = 0; i < 8; ++i) {
        int r = tr + 16 * i;
        float bias = __ldg(b_red + r);
        float v0 = acc[0][i] + bias;
        float v1 = acc[1][i] + bias;
        v0 = v0 > 0.f ? v0 : 0.01f * v0;
        v1 = v1 > 0.f ? v1 : 0.01f * v1;
        out_red[(size_t)(b0 + tb) * RR + r]      = v0;
        out_red[(size_t)(b0 + tb + 16) * RR + r] = v1;
    }
}

// ---------------------------------------------------------------------------
extern "C" void kernel_launch(void* const* d_in, const int* in_sizes, int n_in,
                              void* d_out, int out_size)
{
    (void)in_sizes; (void)n_in; (void)out_size;

    const float* tgt      = (const float*)d_in[0];
    const float* nbr      = (const float*)d_in[1];
    const float* dist     = (const float*)d_in[2];
    const float* beta_p   = (const float*)d_in[3];
    const float* ln_scale = (const float*)d_in[4];
    const float* ln_bias  = (const float*)d_in[5];
    const float* w_self   = (const float*)d_in[6];
    const float* b_self   = (const float*)d_in[7];
    const float* w_nb     = (const float*)d_in[8];
    const float* b_nb     = (const float*)d_in[9];
    const float* w_red    = (const float*)d_in[10];
    const float* b_red    = (const float*)d_in[11];

    float* out       = (float*)d_out;
    float* out_red   = out;                              // B*R
    float* out_selfw = out + (size_t)BB * RR;            // B*D
    float* out_nbw   = out_selfw + (size_t)BB * DD;      // B*K*D

    cudaFuncSetAttribute(gemm_all_kernel,
                         cudaFuncAttributeMaxDynamicSharedMemorySize, GEMM_SMEM);

    wprep_kernel<<<DD * DD / 256, 256>>>(w_self, w_nb);
    ln_kernel<<<(BB * 33) / 8, 256>>>(tgt, nbr, ln_scale, ln_bias);

    // merged: y in [0,1024) -> neighbor GEMM, [1024,1056) -> self GEMM
    gemm_all_kernel<<<dim3(DD / 128, (BB * KK) / 128 + BB / 128), 256, GEMM_SMEM>>>();

    epilogue_kernel<<<BB * 4, 256>>>(dist, beta_p, b_self, b_nb, out_selfw, out_nbw);
    reduce_kernel<<<BB / 32, 256>>>(w_red, b_red, out_red);
}